// round 1
// baseline (speedup 1.0000x reference)
#include <cuda_runtime.h>
#include <cstdint>

#define NND 100000
#define NE  3200000
#define NG  128
#define NH  32

// ---------------- device scratch (allocation-free: __device__ globals) ----------------
__device__ __align__(16) float g_agg1[2 * NND];          // 0.8 MB
__device__ __align__(16) float g_t   [2 * NND];          // 0.8 MB
__device__ __align__(16) float g_agg2[2LL * NND * NH];   // 25.6 MB
__device__ __align__(16) float g_pool[NG * NH];          // 16 KB (signed: graph1 +, graph2 -)

// ---------------- dtype detection: int64 vs int32 index arrays ----------------
// If the array truly holds int64 values < maxval, mid-array 64-bit reads are in range.
// If it holds int32, a 64-bit read combines two values; the hi word is a random
// index (or a sorted-batch tail value ~127) -> out of range with prob ~1-1e-10.
__device__ __forceinline__ bool detect_int64(const void* p, long long nelem,
                                             unsigned long long maxval) {
    const long long* q = (const long long*)p;
    long long a = q[nelem / 2 - 1];
    long long b = q[nelem / 2 - 2];
    return ((unsigned long long)a < maxval) && ((unsigned long long)b < maxval);
}

__device__ __forceinline__ void load_edge(const void* ep, bool is64, long long e,
                                          int& src, int& dst) {
    if (is64) {
        const long long* q = (const long long*)ep;
        src = (int)q[e];
        dst = (int)q[(long long)NE + e];
    } else {
        const int* q = (const int*)ep;
        src = q[e];
        dst = q[NE + e];
    }
}

// ---------------- kernels ----------------

// Zero all accumulators (scratch persists across graph replays -> must re-zero each launch).
__global__ void zero_kernel() {
    long long i = (long long)blockIdx.x * blockDim.x + threadIdx.x;
    float4 z = make_float4(0.f, 0.f, 0.f, 0.f);
    if (i < 2LL * NND * NH / 4) ((float4*)g_agg2)[i] = z;
    if (i < 2 * NND / 4)        ((float4*)g_agg1)[i] = z;
    if (i < NG * NH / 4)        ((float4*)g_pool)[i] = z;
}

// Stage 1: agg1[dst] += x[src]  (scalar scatter, thread per edge, both graphs)
__global__ void edge1_kernel(const float* __restrict__ x1, const void* __restrict__ e1,
                             const float* __restrict__ x2, const void* __restrict__ e2) {
    long long i = (long long)blockIdx.x * blockDim.x + threadIdx.x;
    if (i >= 2LL * NE) return;
    int g = (i >= (long long)NE);
    const void*  ep = g ? e2 : e1;
    const float* x  = g ? x2 : x1;
    bool is64 = detect_int64(ep, 2LL * NE, (unsigned long long)NND);
    long long e = i - (long long)g * NE;
    int src, dst;
    load_edge(ep, is64, e, src, dst);
    atomicAdd(&g_agg1[g * NND + dst], x[src]);
}

// t[i] = x[i] + agg1[i]
__global__ void node_t_kernel(const float* __restrict__ x1, const float* __restrict__ x2) {
    int i = blockIdx.x * blockDim.x + threadIdx.x;
    if (i >= 2 * NND) return;
    int g = (i >= NND);
    const float* x = g ? x2 : x1;
    g_t[i] = x[i - g * NND] + g_agg1[i];
}

// Stage 2: agg2[dst][k] += relu(t[src]*W1[k] + b1[k])
// Warp-cooperative: each warp owns 32 consecutive edges; lane = hidden dim.
// Inner loop broadcasts (t, dst) and issues ONE coalesced 128B RED per edge.
__global__ void edge2_kernel(const void* __restrict__ e1, const void* __restrict__ e2,
                             const float* __restrict__ W1, const float* __restrict__ b1) {
    int lane = threadIdx.x & 31;
    long long warpId = ((long long)blockIdx.x * blockDim.x + threadIdx.x) >> 5;
    long long base = warpId * 32;      // NE % 32 == 0, so no warp straddles graphs
    if (base >= 2LL * NE) return;
    int g = (base >= (long long)NE);
    const void* ep = g ? e2 : e1;
    bool is64 = detect_int64(ep, 2LL * NE, (unsigned long long)NND);
    long long e = base - (long long)g * NE + lane;
    int src, dst;
    load_edge(ep, is64, e, src, dst);
    float t  = g_t[g * NND + src];
    float w1 = W1[lane];
    float bb = b1[lane];
    float* aggb = g_agg2 + (long long)g * NND * NH;
#pragma unroll
    for (int q = 0; q < 32; q++) {
        float tb = __shfl_sync(0xffffffffu, t, q);
        int   db = __shfl_sync(0xffffffffu, dst, q);
        float h = fmaxf(fmaf(tb, w1, bb), 0.f);
        atomicAdd(&aggb[(long long)db * NH + lane], h);   // coalesced RED
    }
}

// Stage 3 + pool: per node v = relu(t*W1+b1)+agg2; out = relu(v@W2+b2);
// accumulate signed into g_pool (batch is sorted -> run-length local accumulation).
__global__ void node_out_kernel(const void* __restrict__ bt1, const void* __restrict__ bt2,
                                const float* __restrict__ W1, const float* __restrict__ b1,
                                const float* __restrict__ W2, const float* __restrict__ b2) {
    __shared__ float W2s[NH * NH];
    for (int i = threadIdx.x; i < NH * NH; i += blockDim.x) W2s[i] = W2[i];
    __syncthreads();

    const int CH = 128;                       // nodes per warp
    const int chunks = (NND + CH - 1) / CH;   // 782
    int lane = threadIdx.x & 31;
    int warp = (blockIdx.x * blockDim.x + threadIdx.x) >> 5;
    if (warp >= 2 * chunks) return;
    int g = (warp >= chunks);
    int c = warp - g * chunks;
    int start = c * CH;
    int end   = min(start + CH, NND);

    const void* bp = g ? bt2 : bt1;
    bool is64 = detect_int64(bp, (long long)NND, (unsigned long long)NG);
    float w1  = W1[lane];
    float bb1 = b1[lane];
    float bb2 = b2[lane];
    float sign = g ? -1.f : 1.f;
    const float* aggb = g_agg2 + (long long)g * NND * NH;
    const float* tb   = g_t + g * NND;

    float poolacc = 0.f;
    int curg = -1;
    for (int i = start; i < end; i++) {
        float a = aggb[(long long)i * NH + lane];   // coalesced 128B
        float t = tb[i];                            // warp-broadcast
        float v = fmaxf(fmaf(t, w1, bb1), 0.f) + a;
        float acc = bb2;
#pragma unroll
        for (int k = 0; k < NH; k++)
            acc = fmaf(__shfl_sync(0xffffffffu, v, k), W2s[k * NH + lane], acc);
        acc = fmaxf(acc, 0.f);
        int bg = is64 ? (int)((const long long*)bp)[i] : ((const int*)bp)[i];
        if (bg != curg) {
            if (curg >= 0) atomicAdd(&g_pool[curg * NH + lane], sign * poolacc);
            poolacc = 0.f;
            curg = bg;
        }
        poolacc += acc;
    }
    if (curg >= 0) atomicAdd(&g_pool[curg * NH + lane], sign * poolacc);
}

__global__ void abs_kernel(float* __restrict__ out) {
    int i = blockIdx.x * blockDim.x + threadIdx.x;
    if (i < NG * NH) out[i] = fabsf(g_pool[i]);
}

// ---------------- launch ----------------
extern "C" void kernel_launch(void* const* d_in, const int* in_sizes, int n_in,
                              void* d_out, int out_size) {
    const float* x1  = (const float*)d_in[0];
    const void*  ei1 = d_in[1];
    const void*  bt1 = d_in[2];
    const float* x2  = (const float*)d_in[3];
    const void*  ei2 = d_in[4];
    const void*  bt2 = d_in[5];
    const float* W1  = (const float*)d_in[6];
    const float* b1  = (const float*)d_in[7];
    const float* W2  = (const float*)d_in[8];
    const float* b2  = (const float*)d_in[9];
    float* out = (float*)d_out;

    zero_kernel<<<(2 * NND * NH / 4 + 255) / 256, 256>>>();
    edge1_kernel<<<(int)((2LL * NE + 255) / 256), 256>>>(x1, ei1, x2, ei2);
    node_t_kernel<<<(2 * NND + 255) / 256, 256>>>(x1, x2);
    edge2_kernel<<<(int)(2LL * NE / 256), 256>>>(ei1, ei2, W1, b1);
    {
        const int chunks = (NND + 127) / 128;
        int warps = 2 * chunks;
        node_out_kernel<<<(warps * 32 + 255) / 256, 256>>>(bt1, bt2, W1, b1, W2, b2);
    }
    abs_kernel<<<(NG * NH + 255) / 256, 256>>>(out);
}

// round 3
// speedup vs baseline: 1.0357x; 1.0357x over previous
#include <cuda_runtime.h>
#include <cstdint>
#include <math_constants.h>

#define NND 100000
#define NE  3200000
#define NG  128
#define NH  32
#define FULL 0xffffffffu

// ---------------- device scratch (allocation-free) ----------------
__device__ __align__(16) float  g_agg1[2 * NND];            // 0.8 MB
__device__ __align__(16) float  g_t   [2 * NND];            // 0.8 MB
__device__ __align__(16) float2 g_bkt [2LL * NND * 33];     // 52.8 MB  (sum,count) per interval
__device__ __align__(16) float  g_pool[NG * NH];            // 16 KB (signed: g1 +, g2 -)
__device__ float g_th[NH];     // sorted thresholds
__device__ int   g_rank[NH];   // rank of threshold k in sorted order

// ---------------- int64 vs int32 index detection ----------------
__device__ __forceinline__ bool detect_int64(const void* p, long long nelem,
                                             unsigned long long maxval) {
    const long long* q = (const long long*)p;
    long long a = q[nelem / 2 - 1];
    long long b = q[nelem / 2 - 2];
    return ((unsigned long long)a < maxval) && ((unsigned long long)b < maxval);
}

__device__ __forceinline__ void load_edge(const void* ep, bool is64, long long e,
                                          int& src, int& dst) {
    if (is64) {
        const long long* q = (const long long*)ep;
        src = (int)q[e];
        dst = (int)q[(long long)NE + e];
    } else {
        const int* q = (const int*)ep;
        src = q[e];
        dst = q[NE + e];
    }
}

// ---------------- kernels ----------------

// Sort thresholds theta_k = -b1k/W1k (W==0 -> +INF sentinel), compute ranks. 1 warp.
__global__ void prep_kernel(const float* __restrict__ W1, const float* __restrict__ b1) {
    int lane = threadIdx.x;
    float w = W1[lane], b = b1[lane];
    float th = (w != 0.f) ? (-b / w) : CUDART_INF_F;
    int r = 0;
#pragma unroll
    for (int i = 0; i < NH; i++) {
        float o = __shfl_sync(FULL, th, i);
        r += (o < th) || (o == th && i < lane);
    }
    g_th[r] = th;
    g_rank[lane] = r;
}

// Zero accumulators (scratch persists across graph replays).
__global__ void zero_kernel() {
    long long i = (long long)blockIdx.x * blockDim.x + threadIdx.x;
    float4 z = make_float4(0.f, 0.f, 0.f, 0.f);
    const long long NB4 = 2LL * NND * 33 * 2 / 4;   // bkt floats /4
    if (i < NB4)          ((float4*)g_bkt)[i] = z;
    if (i < 2 * NND / 4)  ((float4*)g_agg1)[i] = z;
    if (i < NG * NH / 4)  ((float4*)g_pool)[i] = z;
}

// Stage 1: agg1[dst] += x[src]
__global__ void edge1_kernel(const float* __restrict__ x1, const void* __restrict__ e1,
                             const float* __restrict__ x2, const void* __restrict__ e2) {
    long long i = (long long)blockIdx.x * blockDim.x + threadIdx.x;
    if (i >= 2LL * NE) return;
    int g = (i >= (long long)NE);
    const void*  ep = g ? e2 : e1;
    const float* x  = g ? x2 : x1;
    bool is64 = detect_int64(ep, 2LL * NE, (unsigned long long)NND);
    long long e = i - (long long)g * NE;
    int src, dst;
    load_edge(ep, is64, e, src, dst);
    atomicAdd(&g_agg1[g * NND + dst], __ldg(&x[src]));
}

// t[i] = x[i] + agg1[i]
__global__ void node_t_kernel(const float* __restrict__ x1, const float* __restrict__ x2) {
    int i = blockIdx.x * blockDim.x + threadIdx.x;
    if (i >= 2 * NND) return;
    int g = (i >= NND);
    const float* x = g ? x2 : x1;
    g_t[i] = x[i - g * NND] + g_agg1[i];
}

// Stage 2 (bucketed): one float2 atomic (t, 1) per edge into interval bucket of dst.
// Interval index j = #(sorted thresholds <= t) in [0,32], via branchless binary
// search over a bank-replicated shared copy (conflict-free: addr%32 == lane),
// plus one final comparison so j can reach 32 (the R2 bug).
__global__ void edgeb_kernel(const void* __restrict__ e1, const void* __restrict__ e2) {
    __shared__ float th_s[32 * 32];
    for (int i = threadIdx.x; i < 32 * 32; i += blockDim.x) th_s[i] = g_th[i >> 5];
    __syncthreads();

    long long i = (long long)blockIdx.x * blockDim.x + threadIdx.x;
    if (i >= 2LL * NE) return;
    int g = (i >= (long long)NE);
    const void* ep = g ? e2 : e1;
    bool is64 = detect_int64(ep, 2LL * NE, (unsigned long long)NND);
    long long e = i - (long long)g * NE;
    int src, dst;
    load_edge(ep, is64, e, src, dst);
    float t = g_t[g * NND + src];

    int lane = threadIdx.x & 31;
    int j = 0;
#pragma unroll
    for (int s = 16; s >= 1; s >>= 1) {
        int c = j + s;
        if (th_s[((c - 1) << 5) | lane] <= t) j = c;
    }
    // FIX: allow bucket 32 (count can be 0..32; 5 steps only reach 31)
    if (j == 31 && th_s[(31 << 5) | lane] <= t) j = 32;

    float2* p = &g_bkt[((long long)(g * NND + dst)) * 33 + j];
    atomicAdd(p, make_float2(t, 1.f));   // sm_90+ vector atomic
}

// Stage 3 + layer2 + pool. Warp per 8 nodes.
// Per node: suffix-scan 32 interval buckets -> agg2[k] analytically,
// v = relu(t*W1+b1) + agg2, out = relu(v@W2+b2), pooled by sorted batch.
__global__ void __launch_bounds__(256) node_out_kernel(
        const void* __restrict__ bt1, const void* __restrict__ bt2,
        const float* __restrict__ W1, const float* __restrict__ b1,
        const float* __restrict__ W2, const float* __restrict__ b2) {
    const int CH = 8;
    const int chunks = NND / CH;  // 12500
    int lane = threadIdx.x & 31;
    int warp = (blockIdx.x * blockDim.x + threadIdx.x) >> 5;
    if (warp >= 2 * chunks) return;
    int g = (warp >= chunks);
    int c = warp - g * chunks;
    int start = c * CH;

    const void* bp = g ? bt2 : bt1;
    bool is64 = detect_int64(bp, (long long)NND, (unsigned long long)NG);
    float w1  = W1[lane];
    float bb1 = b1[lane];
    float bb2 = b2[lane];
    int   rnk = g_rank[lane];
    float sign = g ? -1.f : 1.f;
    float w2r[NH];
#pragma unroll
    for (int k = 0; k < NH; k++) w2r[k] = W2[k * NH + lane];

    const float* tb = g_t + g * NND;
    float poolacc = 0.f;
    int curg = -1;

    for (int n = start; n < start + CH; n++) {
        const float2* bkt = &g_bkt[((long long)(g * NND + n)) * 33];
        float2 bv = bkt[1 + lane];       // intervals 1..32 on lanes 0..31
        float2 b0 = bkt[0];              // interval 0 (uniform)
        float ss = bv.x, cc = bv.y;
        // inclusive suffix scan: lane j -> sum over intervals >= j+1
#pragma unroll
        for (int off = 1; off < 32; off <<= 1) {
            float s2 = __shfl_down_sync(FULL, ss, off);
            float c2 = __shfl_down_sync(FULL, cc, off);
            if (lane + off < 32) { ss += s2; cc += c2; }
        }
        float TS = b0.x + __shfl_sync(FULL, ss, 0);
        float TC = b0.y + __shfl_sync(FULL, cc, 0);
        float mS = __shfl_sync(FULL, ss, rnk);
        float mC = __shfl_sync(FULL, cc, rnk);
        float agg;
        if (w1 > 0.f)       agg = w1 * mS + bb1 * mC;
        else if (w1 < 0.f)  agg = w1 * (TS - mS) + bb1 * (TC - mC);
        else                agg = fmaxf(bb1, 0.f) * TC;

        float t = tb[n];
        float v = fmaxf(fmaf(t, w1, bb1), 0.f) + agg;

        float acc = bb2;
#pragma unroll
        for (int k = 0; k < NH; k++)
            acc = fmaf(__shfl_sync(FULL, v, k), w2r[k], acc);
        acc = fmaxf(acc, 0.f);

        int bg = is64 ? (int)((const long long*)bp)[n] : ((const int*)bp)[n];
        if (bg != curg) {
            if (curg >= 0) atomicAdd(&g_pool[curg * NH + lane], sign * poolacc);
            poolacc = 0.f;
            curg = bg;
        }
        poolacc += acc;
    }
    if (curg >= 0) atomicAdd(&g_pool[curg * NH + lane], sign * poolacc);
}

__global__ void abs_kernel(float* __restrict__ out) {
    int i = blockIdx.x * blockDim.x + threadIdx.x;
    if (i < NG * NH) out[i] = fabsf(g_pool[i]);
}

// ---------------- launch ----------------
extern "C" void kernel_launch(void* const* d_in, const int* in_sizes, int n_in,
                              void* d_out, int out_size) {
    const float* x1  = (const float*)d_in[0];
    const void*  ei1 = d_in[1];
    const void*  bt1 = d_in[2];
    const float* x2  = (const float*)d_in[3];
    const void*  ei2 = d_in[4];
    const void*  bt2 = d_in[5];
    const float* W1  = (const float*)d_in[6];
    const float* b1  = (const float*)d_in[7];
    const float* W2  = (const float*)d_in[8];
    const float* b2  = (const float*)d_in[9];
    float* out = (float*)d_out;

    prep_kernel<<<1, 32>>>(W1, b1);
    {
        long long n4 = 2LL * NND * 33 * 2 / 4;
        zero_kernel<<<(int)((n4 + 255) / 256), 256>>>();
    }
    edge1_kernel<<<(int)(2LL * NE / 256), 256>>>(x1, ei1, x2, ei2);
    node_t_kernel<<<(2 * NND + 255) / 256, 256>>>(x1, x2);
    edgeb_kernel<<<(int)(2LL * NE / 256), 256>>>(ei1, ei2);
    {
        int warps = 2 * (NND / 8);
        node_out_kernel<<<(warps * 32 + 255) / 256, 256>>>(bt1, bt2, W1, b1, W2, b2);
    }
    abs_kernel<<<(NG * NH + 255) / 256, 256>>>(out);
}

// round 4
// speedup vs baseline: 1.5481x; 1.4947x over previous
#include <cuda_runtime.h>
#include <cstdint>
#include <math_constants.h>

#define NND 100000
#define NE  3200000
#define NG  128
#define NH  32
#define FULL 0xffffffffu

// ---------------- device scratch (allocation-free) ----------------
__device__ __align__(16) float  g_agg1[2 * NND];            // 0.8 MB
__device__ __align__(16) float  g_t   [2 * NND];            // 0.8 MB
__device__ __align__(16) float2 g_bkt [2LL * NND * 33];     // 52.8 MB  (sum,count)/interval
__device__ __align__(16) float  g_pool[NG * NH];            // 16 KB (signed: g1 +, g2 -)
__device__ float g_th[NH];     // sorted thresholds
__device__ int   g_rank[NH];   // rank of threshold k in sorted order

// ---------------- int64 vs int32 index detection ----------------
__device__ __forceinline__ bool detect_int64(const void* p, long long nelem,
                                             unsigned long long maxval) {
    const long long* q = (const long long*)p;
    long long a = q[nelem / 2 - 1];
    long long b = q[nelem / 2 - 2];
    return ((unsigned long long)a < maxval) && ((unsigned long long)b < maxval);
}

// Load 4 consecutive edges (e..e+3, e % 4 == 0) with wide loads.
__device__ __forceinline__ void load_edge4(const void* ep, bool is64, long long e,
                                           int (&src)[4], int (&dst)[4]) {
    if (is64) {
        const longlong2* q = (const longlong2*)ep;
        longlong2 s0 = q[e >> 1], s1 = q[(e >> 1) + 1];
        longlong2 d0 = q[((long long)NE + e) >> 1], d1 = q[(((long long)NE + e) >> 1) + 1];
        src[0] = (int)s0.x; src[1] = (int)s0.y; src[2] = (int)s1.x; src[3] = (int)s1.y;
        dst[0] = (int)d0.x; dst[1] = (int)d0.y; dst[2] = (int)d1.x; dst[3] = (int)d1.y;
    } else {
        const int* qi = (const int*)ep;
        int4 s = ((const int4*)qi)[e >> 2];
        int4 d = ((const int4*)(qi + NE))[e >> 2];
        src[0] = s.x; src[1] = s.y; src[2] = s.z; src[3] = s.w;
        dst[0] = d.x; dst[1] = d.y; dst[2] = d.z; dst[3] = d.w;
    }
}

// ---------------- kernels ----------------

// Sort thresholds theta_k = -b1k/W1k (W==0 -> +INF), compute ranks. 1 warp.
__global__ void prep_kernel(const float* __restrict__ W1, const float* __restrict__ b1) {
    int lane = threadIdx.x;
    float w = W1[lane], b = b1[lane];
    float th = (w != 0.f) ? (-b / w) : CUDART_INF_F;
    int r = 0;
#pragma unroll
    for (int i = 0; i < NH; i++) {
        float o = __shfl_sync(FULL, th, i);
        r += (o < th) || (o == th && i < lane);
    }
    g_th[r] = th;
    g_rank[lane] = r;
}

// Zero accumulators (scratch persists across graph replays).
__global__ void zero_kernel() {
    long long i = (long long)blockIdx.x * blockDim.x + threadIdx.x;
    float4 z = make_float4(0.f, 0.f, 0.f, 0.f);
    const long long NB4 = 2LL * NND * 33 * 2 / 4;
    if (i < NB4)          ((float4*)g_bkt)[i] = z;
    if (i < 2 * NND / 4)  ((float4*)g_agg1)[i] = z;
    if (i < NG * NH / 4)  ((float4*)g_pool)[i] = z;
}

// Stage 1: agg1[dst] += x[src]. ILP-4: 4 edges/thread, independent chains.
__global__ void __launch_bounds__(256) edge1_kernel(
        const float* __restrict__ x1, const void* __restrict__ e1,
        const float* __restrict__ x2, const void* __restrict__ e2) {
    long long tid = (long long)blockIdx.x * blockDim.x + threadIdx.x;
    const long long NT = 2LL * NE / 4;
    if (tid >= NT) return;
    int g = (tid >= NT / 2);
    const void*  ep = g ? e2 : e1;
    const float* x  = g ? x2 : x1;
    bool is64 = detect_int64(ep, 2LL * NE, (unsigned long long)NND);
    long long e = (tid - (long long)g * (NT / 2)) * 4;

    int s[4], d[4];
    load_edge4(ep, is64, e, s, d);
    float xv[4];
#pragma unroll
    for (int u = 0; u < 4; u++) xv[u] = __ldg(&x[s[u]]);
    float* aggb = g_agg1 + g * NND;
#pragma unroll
    for (int u = 0; u < 4; u++) atomicAdd(&aggb[d[u]], xv[u]);
}

// t[i] = x[i] + agg1[i]
__global__ void node_t_kernel(const float* __restrict__ x1, const float* __restrict__ x2) {
    int i = blockIdx.x * blockDim.x + threadIdx.x;
    if (i >= 2 * NND) return;
    int g = (i >= NND);
    const float* x = g ? x2 : x1;
    g_t[i] = x[i - g * NND] + g_agg1[i];
}

// Stage 2 (bucketed): one float2 atomic (t,1) per edge into interval bucket of dst.
// ILP-4. Interval j = #(sorted thresholds <= t) in [0,32]; branchless binary
// search over bank-replicated shared thresholds (conflict-free), + final step to 32.
__global__ void __launch_bounds__(256) edgeb_kernel(
        const void* __restrict__ e1, const void* __restrict__ e2) {
    __shared__ float th_s[32 * 32];
    for (int i = threadIdx.x; i < 32 * 32; i += blockDim.x) th_s[i] = g_th[i >> 5];
    __syncthreads();

    long long tid = (long long)blockIdx.x * blockDim.x + threadIdx.x;
    const long long NT = 2LL * NE / 4;
    if (tid >= NT) return;
    int g = (tid >= NT / 2);
    const void* ep = g ? e2 : e1;
    bool is64 = detect_int64(ep, 2LL * NE, (unsigned long long)NND);
    long long e = (tid - (long long)g * (NT / 2)) * 4;

    int s[4], d[4];
    load_edge4(ep, is64, e, s, d);
    const float* tb = g_t + g * NND;
    float tv[4];
#pragma unroll
    for (int u = 0; u < 4; u++) tv[u] = __ldg(&tb[s[u]]);

    int lane = threadIdx.x & 31;
    float2* bktb = g_bkt + (long long)g * NND * 33;
#pragma unroll
    for (int u = 0; u < 4; u++) {
        float t = tv[u];
        int j = 0;
#pragma unroll
        for (int st = 16; st >= 1; st >>= 1) {
            int c = j + st;
            if (th_s[((c - 1) << 5) | lane] <= t) j = c;
        }
        if (j == 31 && th_s[(31 << 5) | lane] <= t) j = 32;
        atomicAdd(&bktb[(long long)d[u] * 33 + j], make_float2(t, 1.f));
    }
}

// Stage 3 + layer2 + pool. Warp per 8 nodes: suffix-scan 32 interval buckets ->
// agg2[k] analytically; v = relu(t*W1+b1)+agg2; out = relu(v@W2+b2); pooled.
__global__ void __launch_bounds__(256) node_out_kernel(
        const void* __restrict__ bt1, const void* __restrict__ bt2,
        const float* __restrict__ W1, const float* __restrict__ b1,
        const float* __restrict__ W2, const float* __restrict__ b2) {
    const int CH = 8;
    const int chunks = NND / CH;  // 12500
    int lane = threadIdx.x & 31;
    int warp = (blockIdx.x * blockDim.x + threadIdx.x) >> 5;
    if (warp >= 2 * chunks) return;
    int g = (warp >= chunks);
    int c = warp - g * chunks;
    int start = c * CH;

    const void* bp = g ? bt2 : bt1;
    bool is64 = detect_int64(bp, (long long)NND, (unsigned long long)NG);
    float w1  = W1[lane];
    float bb1 = b1[lane];
    float bb2 = b2[lane];
    int   rnk = g_rank[lane];
    float sign = g ? -1.f : 1.f;
    float w2r[NH];
#pragma unroll
    for (int k = 0; k < NH; k++) w2r[k] = W2[k * NH + lane];

    const float* tb = g_t + g * NND;
    float poolacc = 0.f;
    int curg = -1;

    for (int n = start; n < start + CH; n++) {
        const float2* bkt = &g_bkt[((long long)(g * NND + n)) * 33];
        float2 bv = bkt[1 + lane];       // intervals 1..32 on lanes 0..31
        float2 b0 = bkt[0];              // interval 0
        float ss = bv.x, cc = bv.y;
#pragma unroll
        for (int off = 1; off < 32; off <<= 1) {   // inclusive suffix scan
            float s2 = __shfl_down_sync(FULL, ss, off);
            float c2 = __shfl_down_sync(FULL, cc, off);
            if (lane + off < 32) { ss += s2; cc += c2; }
        }
        float TS = b0.x + __shfl_sync(FULL, ss, 0);
        float TC = b0.y + __shfl_sync(FULL, cc, 0);
        float mS = __shfl_sync(FULL, ss, rnk);
        float mC = __shfl_sync(FULL, cc, rnk);
        float agg;
        if (w1 > 0.f)       agg = w1 * mS + bb1 * mC;
        else if (w1 < 0.f)  agg = w1 * (TS - mS) + bb1 * (TC - mC);
        else                agg = fmaxf(bb1, 0.f) * TC;

        float t = tb[n];
        float v = fmaxf(fmaf(t, w1, bb1), 0.f) + agg;

        float acc = bb2;
#pragma unroll
        for (int k = 0; k < NH; k++)
            acc = fmaf(__shfl_sync(FULL, v, k), w2r[k], acc);
        acc = fmaxf(acc, 0.f);

        int bg = is64 ? (int)((const long long*)bp)[n] : ((const int*)bp)[n];
        if (bg != curg) {
            if (curg >= 0) atomicAdd(&g_pool[curg * NH + lane], sign * poolacc);
            poolacc = 0.f;
            curg = bg;
        }
        poolacc += acc;
    }
    if (curg >= 0) atomicAdd(&g_pool[curg * NH + lane], sign * poolacc);
}

__global__ void abs_kernel(float* __restrict__ out) {
    int i = blockIdx.x * blockDim.x + threadIdx.x;
    if (i < NG * NH) out[i] = fabsf(g_pool[i]);
}

// ---------------- launch ----------------
extern "C" void kernel_launch(void* const* d_in, const int* in_sizes, int n_in,
                              void* d_out, int out_size) {
    const float* x1  = (const float*)d_in[0];
    const void*  ei1 = d_in[1];
    const void*  bt1 = d_in[2];
    const float* x2  = (const float*)d_in[3];
    const void*  ei2 = d_in[4];
    const void*  bt2 = d_in[5];
    const float* W1  = (const float*)d_in[6];
    const float* b1  = (const float*)d_in[7];
    const float* W2  = (const float*)d_in[8];
    const float* b2  = (const float*)d_in[9];
    float* out = (float*)d_out;

    prep_kernel<<<1, 32>>>(W1, b1);
    {
        long long n4 = 2LL * NND * 33 * 2 / 4;
        zero_kernel<<<(int)((n4 + 255) / 256), 256>>>();
    }
    {
        long long nt = 2LL * NE / 4;
        edge1_kernel<<<(int)((nt + 255) / 256), 256>>>(x1, ei1, x2, ei2);
    }
    node_t_kernel<<<(2 * NND + 255) / 256, 256>>>(x1, x2);
    {
        long long nt = 2LL * NE / 4;
        edgeb_kernel<<<(int)((nt + 255) / 256), 256>>>(ei1, ei2);
    }
    {
        int warps = 2 * (NND / 8);
        node_out_kernel<<<(warps * 32 + 255) / 256, 256>>>(bt1, bt2, W1, b1, W2, b2);
    }
    abs_kernel<<<(NG * NH + 255) / 256, 256>>>(out);
}